// round 2
// baseline (speedup 1.0000x reference)
#include <cuda_runtime.h>
#include <math.h>

// Problem constants (fixed by the dataset shapes)
#define BB   8
#define TT   100
#define MTOT 800          // B*T
#define HH   1024         // hidden
#define LL   512          // encoder length
#define VV   32000        // vocab

// GEMM tiling
#define BM 128
#define BN 128
#define BK 32

// Scratch (no cudaMalloc allowed): logits [800, 32000] fp32 = 102.4 MB
__device__ float g_logits[(size_t)MTOT * VV];
__device__ float g_pgen[MTOT];
__device__ float g_rmax[MTOT];
__device__ float g_rsum[MTOT];

__device__ __forceinline__ unsigned f2tf32(float x) {
    unsigned r;
    asm("cvt.rna.tf32.f32 %0, %1;" : "=r"(r) : "f"(x));
    return r;
}

// ---------------------------------------------------------------------------
// Kernel 1: p_gen[row] = sigmoid(dot(x[row], w_gen) + b_gen)
// ---------------------------------------------------------------------------
__global__ void pgen_kernel(const float* __restrict__ x,
                            const float* __restrict__ w_gen,
                            const float* __restrict__ b_gen) {
    int row = blockIdx.x;
    const float* xr = x + (size_t)row * HH;
    float s = 0.f;
    for (int i = threadIdx.x; i < HH; i += 256)
        s += xr[i] * w_gen[i];
    __shared__ float red[256];
    red[threadIdx.x] = s;
    __syncthreads();
    for (int off = 128; off > 0; off >>= 1) {
        if (threadIdx.x < off) red[threadIdx.x] += red[threadIdx.x + off];
        __syncthreads();
    }
    if (threadIdx.x == 0) {
        float z = red[0] + b_gen[0];
        g_pgen[row] = 1.f / (1.f + expf(-z));
    }
}

// ---------------------------------------------------------------------------
// Kernel 2: tf32 GEMM  g_logits[m, v] = sum_k x[m,k] * W[k,v] + bias[v]
// 128x128 block tile, BK=32, 8 warps (2x4), each warp 64x32 via m16n8k8 tf32.
// Smem pads chosen so fragment LDS are conflict-free: (4g + t) spans 32 banks.
// ---------------------------------------------------------------------------
__global__ __launch_bounds__(256) void gemm_tf32(const float* __restrict__ A,
                                                 const float* __restrict__ W,
                                                 const float* __restrict__ bias) {
    __shared__ float As[BM][BK + 4];  // 128 x 36 floats
    __shared__ float Bs[BK][BN + 4];  // 32  x 132 floats

    const int tid   = threadIdx.x;
    const int lane  = tid & 31;
    const int warp  = tid >> 5;
    const int warpM = warp >> 2;   // 0..1
    const int warpN = warp & 3;    // 0..3
    const int g     = lane >> 2;   // groupID 0..7
    const int t     = lane & 3;    // thread-in-group 0..3
    const int m0    = blockIdx.y * BM;
    const int n0    = blockIdx.x * BN;

    float acc[4][4][4];
#pragma unroll
    for (int i = 0; i < 4; i++)
#pragma unroll
        for (int j = 0; j < 4; j++)
#pragma unroll
            for (int k = 0; k < 4; k++) acc[i][j][k] = 0.f;

    for (int k0 = 0; k0 < HH; k0 += BK) {
        // Stage A tile (128x32): 1024 float4 slots, 4 per thread
#pragma unroll
        for (int i = 0; i < 4; i++) {
            int s  = tid + i * 256;
            int r  = s >> 3;       // 8 float4 per row
            int c4 = s & 7;
            float4 v = make_float4(0.f, 0.f, 0.f, 0.f);
            int gr = m0 + r;
            if (gr < MTOT)
                v = *reinterpret_cast<const float4*>(A + (size_t)gr * HH + k0 + c4 * 4);
            float4 w;
            w.x = __uint_as_float(f2tf32(v.x));
            w.y = __uint_as_float(f2tf32(v.y));
            w.z = __uint_as_float(f2tf32(v.z));
            w.w = __uint_as_float(f2tf32(v.w));
            *reinterpret_cast<float4*>(&As[r][c4 * 4]) = w;
        }
        // Stage B tile (32x128): 1024 float4 slots
#pragma unroll
        for (int i = 0; i < 4; i++) {
            int s  = tid + i * 256;
            int kk = s >> 5;       // 32 float4 per k-row
            int c4 = s & 31;
            float4 v = *reinterpret_cast<const float4*>(W + (size_t)(k0 + kk) * VV + n0 + c4 * 4);
            float4 w;
            w.x = __uint_as_float(f2tf32(v.x));
            w.y = __uint_as_float(f2tf32(v.y));
            w.z = __uint_as_float(f2tf32(v.z));
            w.w = __uint_as_float(f2tf32(v.w));
            *reinterpret_cast<float4*>(&Bs[kk][c4 * 4]) = w;
        }
        __syncthreads();

#pragma unroll
        for (int kk = 0; kk < BK; kk += 8) {
            unsigned a[4][4], b[4][2];
#pragma unroll
            for (int mi = 0; mi < 4; mi++) {
                int r = warpM * 64 + mi * 16;
                a[mi][0] = __float_as_uint(As[r + g][kk + t]);
                a[mi][1] = __float_as_uint(As[r + 8 + g][kk + t]);
                a[mi][2] = __float_as_uint(As[r + g][kk + t + 4]);
                a[mi][3] = __float_as_uint(As[r + 8 + g][kk + t + 4]);
            }
#pragma unroll
            for (int ni = 0; ni < 4; ni++) {
                int c = warpN * 32 + ni * 8;
                b[ni][0] = __float_as_uint(Bs[kk + t][c + g]);
                b[ni][1] = __float_as_uint(Bs[kk + 4 + t][c + g]);
            }
#pragma unroll
            for (int mi = 0; mi < 4; mi++)
#pragma unroll
                for (int ni = 0; ni < 4; ni++) {
                    asm volatile(
                        "mma.sync.aligned.m16n8k8.row.col.f32.tf32.tf32.f32 "
                        "{%0,%1,%2,%3}, {%4,%5,%6,%7}, {%8,%9}, {%0,%1,%2,%3};"
                        : "+f"(acc[mi][ni][0]), "+f"(acc[mi][ni][1]),
                          "+f"(acc[mi][ni][2]), "+f"(acc[mi][ni][3])
                        : "r"(a[mi][0]), "r"(a[mi][1]), "r"(a[mi][2]), "r"(a[mi][3]),
                          "r"(b[ni][0]), "r"(b[ni][1]));
                }
        }
        __syncthreads();
    }

    // Epilogue: add bias, write logits scratch
#pragma unroll
    for (int ni = 0; ni < 4; ni++) {
        int c = n0 + warpN * 32 + ni * 8 + 2 * t;
        float b0 = bias[c];
        float b1 = bias[c + 1];
#pragma unroll
        for (int mi = 0; mi < 4; mi++) {
            int r = m0 + warpM * 64 + mi * 16 + g;
            if (r < MTOT) {
                g_logits[(size_t)r * VV + c]     = acc[mi][ni][0] + b0;
                g_logits[(size_t)r * VV + c + 1] = acc[mi][ni][1] + b1;
            }
            if (r + 8 < MTOT) {
                g_logits[(size_t)(r + 8) * VV + c]     = acc[mi][ni][2] + b0;
                g_logits[(size_t)(r + 8) * VV + c + 1] = acc[mi][ni][3] + b1;
            }
        }
    }
}

// ---------------------------------------------------------------------------
// Kernel 3: per-row online softmax stats (max, sum of exp) over V=32000
// ---------------------------------------------------------------------------
__global__ void rowstats_kernel() {
    int row = blockIdx.x;
    const float* lr = g_logits + (size_t)row * VV;
    float m = -1e30f, s = 0.f;
    for (int v = threadIdx.x; v < VV; v += 256) {
        float l = lr[v];
        if (l > m) {
            s = s * expf(m - l) + 1.f;
            m = l;
        } else {
            s += expf(l - m);
        }
    }
    __shared__ float sm[256], ss[256];
    sm[threadIdx.x] = m;
    ss[threadIdx.x] = s;
    __syncthreads();
    for (int off = 128; off > 0; off >>= 1) {
        if (threadIdx.x < off) {
            float m1 = sm[threadIdx.x], s1 = ss[threadIdx.x];
            float m2 = sm[threadIdx.x + off], s2 = ss[threadIdx.x + off];
            float M = fmaxf(m1, m2);
            sm[threadIdx.x] = M;
            ss[threadIdx.x] = s1 * expf(m1 - M) + s2 * expf(m2 - M);
        }
        __syncthreads();
    }
    if (threadIdx.x == 0) {
        g_rmax[row] = sm[0];
        g_rsum[row] = ss[0];
    }
}

// ---------------------------------------------------------------------------
// Kernel 4: out[row, v] = p_gen[row] * exp(logit - max) / sum
// ---------------------------------------------------------------------------
__global__ void vocab_kernel(float* __restrict__ out) {
    int row = blockIdx.y;
    int v   = blockIdx.x * 256 + threadIdx.x;
    float scale = g_pgen[row] / g_rsum[row];
    float m     = g_rmax[row];
    size_t i = (size_t)row * VV + v;
    out[i] = scale * expf(g_logits[i] - m);
}

// ---------------------------------------------------------------------------
// Kernel 5: copy-distribution scatter:
//   out[row, enc[b, l]] += (1 - p_gen[row]) * softmax(attn[row])[l]
// ---------------------------------------------------------------------------
__global__ void scatter_kernel(const float* __restrict__ attn,
                               const int* __restrict__ enc,
                               float* __restrict__ out) {
    int row = blockIdx.x;          // 0..799
    int b   = row / TT;
    const float* ar = attn + (size_t)row * LL;

    __shared__ float av[LL];
    __shared__ float red[256];

    float m = -1e30f;
    for (int l = threadIdx.x; l < LL; l += 256) {
        float a = ar[l];
        av[l] = a;
        m = fmaxf(m, a);
    }
    red[threadIdx.x] = m;
    __syncthreads();
    for (int off = 128; off > 0; off >>= 1) {
        if (threadIdx.x < off)
            red[threadIdx.x] = fmaxf(red[threadIdx.x], red[threadIdx.x + off]);
        __syncthreads();
    }
    m = red[0];
    __syncthreads();

    float s = 0.f;
    for (int l = threadIdx.x; l < LL; l += 256)
        s += expf(av[l] - m);
    red[threadIdx.x] = s;
    __syncthreads();
    for (int off = 128; off > 0; off >>= 1) {
        if (threadIdx.x < off) red[threadIdx.x] += red[threadIdx.x + off];
        __syncthreads();
    }
    s = red[0];

    float scale = (1.f - g_pgen[row]) / s;
    for (int l = threadIdx.x; l < LL; l += 256) {
        float val = scale * expf(av[l] - m);
        int idx = enc[b * LL + l];
        atomicAdd(&out[(size_t)row * VV + idx], val);
    }
}

// ---------------------------------------------------------------------------
// Kernel 6: out = log(out)
// ---------------------------------------------------------------------------
__global__ void log_kernel(float* __restrict__ out) {
    size_t i = (size_t)blockIdx.x * 256 + threadIdx.x;
    out[i] = logf(out[i]);
}

// ---------------------------------------------------------------------------
extern "C" void kernel_launch(void* const* d_in, const int* in_sizes, int n_in,
                              void* d_out, int out_size) {
    const float* x    = (const float*)d_in[0];  // [8,100,1024]
    const float* attn = (const float*)d_in[1];  // [8,100,512]
    const int*   enc  = (const int*)  d_in[2];  // [8,512]
    const float* Wv   = (const float*)d_in[3];  // [1024,32000]
    const float* bv   = (const float*)d_in[4];  // [32000]
    const float* wg   = (const float*)d_in[5];  // [1024,1]
    const float* bg   = (const float*)d_in[6];  // [1]
    float* out = (float*)d_out;                 // [8,100,32000]

    pgen_kernel<<<MTOT, 256>>>(x, wg, bg);

    dim3 ggrid(VV / BN, (MTOT + BM - 1) / BM);  // (250, 7)
    gemm_tf32<<<ggrid, 256>>>(x, Wv, bv);

    rowstats_kernel<<<MTOT, 256>>>();

    dim3 vgrid(VV / 256, MTOT);                 // (125, 800)
    vocab_kernel<<<vgrid, 256>>>(out);

    scatter_kernel<<<MTOT, 256>>>(attn, enc, out);

    int nblk = (int)(((size_t)MTOT * VV) / 256); // 100000
    log_kernel<<<nblk, 256>>>(out);
}

// round 3
// speedup vs baseline: 1.0377x; 1.0377x over previous
#include <cuda_runtime.h>
#include <math.h>

#define BB   8
#define TT   100
#define MTOT 800
#define HH   1024
#define LL   512
#define VV   32000
#define V4   (VV / 4)      // 8000

// GEMM tiling
#define BM 256
#define BN 128
#define BK 16
#define NK (HH / BK)       // 64
#define GEMM_THREADS 512

// smem layout (floats): A stages [2][256][20], B stages [2][16][136]
#define A_PITCH 20
#define B_PITCH 136
#define A_STAGE (BM * A_PITCH)          // 5120
#define B_STAGE (BK * B_PITCH)          // 2176
#define SMEM_FLOATS (2 * A_STAGE + 2 * B_STAGE)
#define SMEM_BYTES (SMEM_FLOATS * 4)    // 58368

// Scratch (no cudaMalloc allowed)
__device__ float g_logits[(size_t)MTOT * VV];   // 102.4 MB
__device__ float g_pgen[MTOT];
__device__ float g_scale[MTOT];
__device__ float g_rmax[MTOT];

// ---------------------------------------------------------------------------
// cp.async helpers
// ---------------------------------------------------------------------------
__device__ __forceinline__ void cp_async16(float* smem_dst, const float* gsrc) {
    unsigned saddr = (unsigned)__cvta_generic_to_shared(smem_dst);
    asm volatile("cp.async.cg.shared.global [%0], [%1], 16;\n" ::"r"(saddr), "l"(gsrc));
}
__device__ __forceinline__ void cp_async_commit() {
    asm volatile("cp.async.commit_group;\n");
}
template <int N>
__device__ __forceinline__ void cp_async_wait() {
    asm volatile("cp.async.wait_group %0;\n" ::"n"(N));
}

// ---------------------------------------------------------------------------
// Kernel 1: p_gen[row] = sigmoid(dot(x[row], w_gen) + b_gen)
// ---------------------------------------------------------------------------
__global__ void pgen_kernel(const float* __restrict__ x,
                            const float* __restrict__ w_gen,
                            const float* __restrict__ b_gen) {
    int row = blockIdx.x;
    const float4* xr = (const float4*)(x + (size_t)row * HH);
    const float4* wr = (const float4*)w_gen;
    float s = 0.f;
    for (int i = threadIdx.x; i < HH / 4; i += 256) {
        float4 a = xr[i], b = wr[i];
        s += a.x * b.x + a.y * b.y + a.z * b.z + a.w * b.w;
    }
    __shared__ float red[256];
    red[threadIdx.x] = s;
    __syncthreads();
    for (int off = 128; off > 0; off >>= 1) {
        if (threadIdx.x < off) red[threadIdx.x] += red[threadIdx.x + off];
        __syncthreads();
    }
    if (threadIdx.x == 0) {
        float z = red[0] + b_gen[0];
        g_pgen[row] = 1.f / (1.f + expf(-z));
    }
}

// ---------------------------------------------------------------------------
// Kernel 2: tf32 GEMM, 256x128 tile, BK=16, cp.async double buffer.
// 16 warps: warpM = warp&3 (64 rows each), warpN = warp>>2 (32 cols each).
// Grid: (m-tiles=4, n-tiles=250), m fastest => W slice reused via L2.
// ---------------------------------------------------------------------------
__global__ __launch_bounds__(GEMM_THREADS, 1)
void gemm_tf32(const float* __restrict__ A,
               const float* __restrict__ W,
               const float* __restrict__ bias) {
    extern __shared__ float smem[];
    float* As = smem;                 // [2][BM][A_PITCH]
    float* Bs = smem + 2 * A_STAGE;   // [2][BK][B_PITCH]

    const int tid   = threadIdx.x;
    const int lane  = tid & 31;
    const int warp  = tid >> 5;
    const int warpM = warp & 3;
    const int warpN = warp >> 2;
    const int g     = lane >> 2;      // 0..7
    const int t     = lane & 3;       // 0..3
    const int m0    = blockIdx.x * BM;
    const int n0    = blockIdx.y * BN;

    float acc[4][4][4];
#pragma unroll
    for (int i = 0; i < 4; i++)
#pragma unroll
        for (int j = 0; j < 4; j++)
#pragma unroll
            for (int k = 0; k < 4; k++) acc[i][j][k] = 0.f;

    // staging lambda-equivalents
    // A tile: 256x16 floats = 1024 float4, 2 per thread
    // B tile: 16x128 floats = 512 float4, 1 per thread
    const int ar0  = (tid) >> 2,        ac0 = (tid & 3) * 4;
    const int ar1  = (tid + 512) >> 2,  ac1 = ((tid + 512) & 3) * 4;
    const int bkk  = tid >> 5,          bc  = (tid & 31) * 4;
    // clamp A row so OOB m-tiles read valid memory (values unused)
    const int garow0 = (m0 + ar0 < MTOT) ? (m0 + ar0) : (MTOT - 1);
    const int garow1 = (m0 + ar1 < MTOT) ? (m0 + ar1) : (MTOT - 1);

    // prefetch stage 0
    {
        const int kg = 0;
        cp_async16(As + ar0 * A_PITCH + ac0, A + (size_t)garow0 * HH + kg + ac0);
        cp_async16(As + ar1 * A_PITCH + ac1, A + (size_t)garow1 * HH + kg + ac1);
        cp_async16(Bs + bkk * B_PITCH + bc, W + (size_t)(kg + bkk) * VV + n0 + bc);
        cp_async_commit();
    }

    for (int k0 = 0; k0 < NK; k0++) {
        const int cur = k0 & 1;
        const int nxt = cur ^ 1;
        if (k0 + 1 < NK) {
            const int kg = (k0 + 1) * BK;
            cp_async16(As + nxt * A_STAGE + ar0 * A_PITCH + ac0,
                       A + (size_t)garow0 * HH + kg + ac0);
            cp_async16(As + nxt * A_STAGE + ar1 * A_PITCH + ac1,
                       A + (size_t)garow1 * HH + kg + ac1);
            cp_async16(Bs + nxt * B_STAGE + bkk * B_PITCH + bc,
                       W + (size_t)(kg + bkk) * VV + n0 + bc);
            cp_async_commit();
            cp_async_wait<1>();
        } else {
            cp_async_wait<0>();
        }
        __syncthreads();

        const float* Ab = As + cur * A_STAGE + (warpM * 64) * A_PITCH;
        const float* Bb = Bs + cur * B_STAGE + warpN * 32;

#pragma unroll
        for (int kk = 0; kk < BK; kk += 8) {
            unsigned a[4][4], b[4][2];
#pragma unroll
            for (int mi = 0; mi < 4; mi++) {
                const float* ap = Ab + (mi * 16 + g) * A_PITCH + kk + t;
                a[mi][0] = __float_as_uint(ap[0]);
                a[mi][1] = __float_as_uint(ap[8 * A_PITCH]);
                a[mi][2] = __float_as_uint(ap[4]);
                a[mi][3] = __float_as_uint(ap[8 * A_PITCH + 4]);
            }
#pragma unroll
            for (int ni = 0; ni < 4; ni++) {
                const float* bp = Bb + (kk + t) * B_PITCH + ni * 8 + g;
                b[ni][0] = __float_as_uint(bp[0]);
                b[ni][1] = __float_as_uint(bp[4 * B_PITCH]);
            }
#pragma unroll
            for (int mi = 0; mi < 4; mi++)
#pragma unroll
                for (int ni = 0; ni < 4; ni++) {
                    asm volatile(
                        "mma.sync.aligned.m16n8k8.row.col.f32.tf32.tf32.f32 "
                        "{%0,%1,%2,%3}, {%4,%5,%6,%7}, {%8,%9}, {%0,%1,%2,%3};"
                        : "+f"(acc[mi][ni][0]), "+f"(acc[mi][ni][1]),
                          "+f"(acc[mi][ni][2]), "+f"(acc[mi][ni][3])
                        : "r"(a[mi][0]), "r"(a[mi][1]), "r"(a[mi][2]), "r"(a[mi][3]),
                          "r"(b[ni][0]), "r"(b[ni][1]));
                }
        }
        __syncthreads();
    }

    // Epilogue: bias + write logits
#pragma unroll
    for (int ni = 0; ni < 4; ni++) {
        int c = n0 + warpN * 32 + ni * 8 + 2 * t;
        float2 bb = *reinterpret_cast<const float2*>(bias + c);
#pragma unroll
        for (int mi = 0; mi < 4; mi++) {
            int r = m0 + warpM * 64 + mi * 16 + g;
            if (r < MTOT) {
                float2 v = make_float2(acc[mi][ni][0] + bb.x, acc[mi][ni][1] + bb.y);
                *reinterpret_cast<float2*>(g_logits + (size_t)r * VV + c) = v;
            }
            if (r + 8 < MTOT) {
                float2 v = make_float2(acc[mi][ni][2] + bb.x, acc[mi][ni][3] + bb.y);
                *reinterpret_cast<float2*>(g_logits + (size_t)(r + 8) * VV + c) = v;
            }
        }
    }
}

// ---------------------------------------------------------------------------
// Kernel 3: per-row softmax stats over V (vectorized); g_scale = pgen/sum
// ---------------------------------------------------------------------------
__global__ void rowstats_kernel() {
    int row = blockIdx.x;
    const float4* lr = (const float4*)(g_logits + (size_t)row * VV);
    float m = -1e30f, s = 0.f;
    for (int i = threadIdx.x; i < V4; i += 256) {
        float4 v = lr[i];
#pragma unroll
        for (int j = 0; j < 4; j++) {
            float l = (j == 0) ? v.x : (j == 1) ? v.y : (j == 2) ? v.z : v.w;
            if (l > m) {
                s = s * expf(m - l) + 1.f;
                m = l;
            } else {
                s += expf(l - m);
            }
        }
    }
    __shared__ float sm[256], ss[256];
    sm[threadIdx.x] = m;
    ss[threadIdx.x] = s;
    __syncthreads();
    for (int off = 128; off > 0; off >>= 1) {
        if (threadIdx.x < off) {
            float m1 = sm[threadIdx.x], s1 = ss[threadIdx.x];
            float m2 = sm[threadIdx.x + off], s2 = ss[threadIdx.x + off];
            float M = fmaxf(m1, m2);
            sm[threadIdx.x] = M;
            ss[threadIdx.x] = s1 * expf(m1 - M) + s2 * expf(m2 - M);
        }
        __syncthreads();
    }
    if (threadIdx.x == 0) {
        g_rmax[row] = sm[0];
        g_scale[row] = g_pgen[row] / ss[0];
    }
}

// ---------------------------------------------------------------------------
// Kernel 4: zero row slice of out, then scatter copy-dist into it.
//   out[row, enc[b, l]] += (1 - p_gen[row]) * softmax(attn[row])[l]
// Row-local: no cross-block hazards.
// ---------------------------------------------------------------------------
__global__ void scatter_kernel(const float* __restrict__ attn,
                               const int* __restrict__ enc,
                               float* __restrict__ out) {
    int row = blockIdx.x;
    int b   = row / TT;
    const float* ar = attn + (size_t)row * LL;

    // zero this row's out slice
    float4* o4 = (float4*)(out + (size_t)row * VV);
    float4 z = make_float4(0.f, 0.f, 0.f, 0.f);
    for (int i = threadIdx.x; i < V4; i += 256) o4[i] = z;

    __shared__ float av[LL];
    __shared__ float red[256];

    float m = -1e30f;
    for (int l = threadIdx.x; l < LL; l += 256) {
        float a = ar[l];
        av[l] = a;
        m = fmaxf(m, a);
    }
    red[threadIdx.x] = m;
    __syncthreads();
    for (int off = 128; off > 0; off >>= 1) {
        if (threadIdx.x < off)
            red[threadIdx.x] = fmaxf(red[threadIdx.x], red[threadIdx.x + off]);
        __syncthreads();
    }
    m = red[0];
    __syncthreads();

    float s = 0.f;
    for (int l = threadIdx.x; l < LL; l += 256) s += expf(av[l] - m);
    red[threadIdx.x] = s;
    __syncthreads();
    for (int off = 128; off > 0; off >>= 1) {
        if (threadIdx.x < off) red[threadIdx.x] += red[threadIdx.x + off];
        __syncthreads();
    }
    s = red[0];

    float scale = (1.f - g_pgen[row]) / s;
    for (int l = threadIdx.x; l < LL; l += 256) {
        float val = scale * expf(av[l] - m);
        int idx = enc[b * LL + l];
        atomicAdd(&out[(size_t)row * VV + idx], val);
    }
}

// ---------------------------------------------------------------------------
// Kernel 5: fused vocab + log:
//   out = log(out_copy + scale[row] * exp(logit - rmax[row]))
// ---------------------------------------------------------------------------
__global__ void final_kernel(float* __restrict__ out) {
    const size_t total4 = (size_t)MTOT * V4;   // 6.4M float4
    const float4* l4 = (const float4*)g_logits;
    float4* o4 = (float4*)out;
    for (size_t i = (size_t)blockIdx.x * blockDim.x + threadIdx.x; i < total4;
         i += (size_t)gridDim.x * blockDim.x) {
        int row = (int)(i / V4);
        float scale = g_scale[row];
        float m = g_rmax[row];
        float4 l = l4[i];
        float4 o = o4[i];
        o.x = logf(o.x + scale * expf(l.x - m));
        o.y = logf(o.y + scale * expf(l.y - m));
        o.z = logf(o.z + scale * expf(l.z - m));
        o.w = logf(o.w + scale * expf(l.w - m));
        o4[i] = o;
    }
}

// ---------------------------------------------------------------------------
extern "C" void kernel_launch(void* const* d_in, const int* in_sizes, int n_in,
                              void* d_out, int out_size) {
    const float* x    = (const float*)d_in[0];  // [8,100,1024]
    const float* attn = (const float*)d_in[1];  // [8,100,512]
    const int*   enc  = (const int*)  d_in[2];  // [8,512]
    const float* Wv   = (const float*)d_in[3];  // [1024,32000]
    const float* bv   = (const float*)d_in[4];  // [32000]
    const float* wg   = (const float*)d_in[5];  // [1024,1]
    const float* bg   = (const float*)d_in[6];  // [1]
    float* out = (float*)d_out;                 // [8,100,32000]

    static bool attr_set = false;
    if (!attr_set) {
        cudaFuncSetAttribute(gemm_tf32, cudaFuncAttributeMaxDynamicSharedMemorySize,
                             SMEM_BYTES);
        attr_set = true;
    }

    pgen_kernel<<<MTOT, 256>>>(x, wg, bg);

    dim3 ggrid((MTOT + BM - 1) / BM, VV / BN);  // (4, 250), m-tile fastest
    gemm_tf32<<<ggrid, GEMM_THREADS, SMEM_BYTES>>>(x, Wv, bv);

    rowstats_kernel<<<MTOT, 256>>>();

    scatter_kernel<<<MTOT, 256>>>(attn, enc, out);

    final_kernel<<<2048, 256>>>(out);
}